// round 1
// baseline (speedup 1.0000x reference)
#include <cuda_runtime.h>

// CircleProjectionLayer: z = center + (x - center) * min(1, R / max(||x-center||, 1e-12))
// RADIUS = 1.0, B = 8388608 points, [B,3] float32 layout.
//
// Strategy: 4 points = 48 bytes = 3 aligned float4 per tensor per thread.
// Pure streaming kernel; HBM-bound, target ~45 us.

__global__ void __launch_bounds__(256)
circle_proj_kernel(const float4* __restrict__ x4,
                   const float4* __restrict__ c4,
                   float4* __restrict__ o4,
                   int n_quads)  // n_quads = B/4 groups of 4 points
{
    int i = blockIdx.x * blockDim.x + threadIdx.x;
    if (i >= n_quads) return;

    long base = 3L * i;
    // Front-batch all 6 loads (MLP=6) before any math.
    float4 xa = x4[base + 0];
    float4 xb = x4[base + 1];
    float4 xc = x4[base + 2];
    float4 ca = c4[base + 0];
    float4 cb = c4[base + 1];
    float4 cc = c4[base + 2];

    float xs[12] = {xa.x, xa.y, xa.z, xa.w,
                    xb.x, xb.y, xb.z, xb.w,
                    xc.x, xc.y, xc.z, xc.w};
    float cs[12] = {ca.x, ca.y, ca.z, ca.w,
                    cb.x, cb.y, cb.z, cb.w,
                    cc.x, cc.y, cc.z, cc.w};
    float os[12];

#pragma unroll
    for (int p = 0; p < 4; p++) {
        float dx = xs[3 * p + 0] - cs[3 * p + 0];
        float dy = xs[3 * p + 1] - cs[3 * p + 1];
        float dz = xs[3 * p + 2] - cs[3 * p + 2];
        float n2 = fmaf(dx, dx, fmaf(dy, dy, dz * dz));
        // RADIUS = 1: scale = min(1, 1/||d||); rsqrtf(0)=inf -> scale=1 -> z=x. Matches ref.
        float s = fminf(1.0f, rsqrtf(n2));
        os[3 * p + 0] = fmaf(dx, s, cs[3 * p + 0]);
        os[3 * p + 1] = fmaf(dy, s, cs[3 * p + 1]);
        os[3 * p + 2] = fmaf(dz, s, cs[3 * p + 2]);
    }

    o4[base + 0] = make_float4(os[0], os[1], os[2],  os[3]);
    o4[base + 1] = make_float4(os[4], os[5], os[6],  os[7]);
    o4[base + 2] = make_float4(os[8], os[9], os[10], os[11]);
}

extern "C" void kernel_launch(void* const* d_in, const int* in_sizes, int n_in,
                              void* d_out, int out_size)
{
    const float4* x4 = (const float4*)d_in[0];      // x: [B,3] f32
    const float4* c4 = (const float4*)d_in[1];      // center: [B,3] f32
    float4* o4 = (float4*)d_out;                    // out: [B,3] f32

    int n_elems = in_sizes[0];        // B*3 = 25165824
    int n_points = n_elems / 3;       // 8388608
    int n_quads = n_points / 4;       // 2097152 (B divisible by 4)

    int threads = 256;
    int blocks = (n_quads + threads - 1) / threads;
    circle_proj_kernel<<<blocks, threads>>>(x4, c4, o4, n_quads);
}